// round 1
// baseline (speedup 1.0000x reference)
#include <cuda_runtime.h>
#include <math.h>

// Problem constants
#define BATCH 2
#define SEQ   2048
#define HQ    32
#define HKV   8
#define DH    128
#define GROUPS (HQ / HKV)

// Tiling
#define BQ 64
#define BK 64
#define QT_STRIDE 68   // padded column count for transposed Q/K tiles
#define PS_STRIDE 68   // padded stride for P tile

// Scratch (device globals: allocation-free contract)
__device__ float g_Qr[(size_t)BATCH * HQ  * SEQ * DH];  // RoPE'd Q, layout [b][h][s][d]
__device__ float g_Kr[(size_t)BATCH * HKV * SEQ * DH];  // RoPE'd K, layout [b][hk][s][d]
__device__ float g_Vr[(size_t)BATCH * HKV * SEQ * DH];  // V,        layout [b][hk][s][d]

// ---------------------------------------------------------------------------
// RoPE kernels: x*cos + rotate_half(x)*sin, and transpose to [b][h][s][d]
// ---------------------------------------------------------------------------
__global__ void rope_q_kernel(const float* __restrict__ q,
                              const float* __restrict__ cosb,
                              const float* __restrict__ sinb) {
    int i = blockIdx.x * blockDim.x + threadIdx.x;
    const int total = BATCH * SEQ * HQ * (DH / 2);
    if (i >= total) return;
    int d    = i & 63;
    int rest = i >> 6;            // ((b*SEQ + s)*HQ + h)
    int h = rest % HQ;
    int s = (rest / HQ) % SEQ;
    int b = rest / (HQ * SEQ);

    size_t in_base = ((size_t)(b * SEQ + s) * HQ + h) * DH;
    float x0 = q[in_base + d];
    float x1 = q[in_base + d + 64];
    float c  = cosb[s * DH + d];
    float sn = sinb[s * DH + d];

    size_t out_base = ((size_t)(b * HQ + h) * SEQ + s) * DH;
    g_Qr[out_base + d]      = x0 * c - x1 * sn;
    g_Qr[out_base + d + 64] = x1 * c + x0 * sn;
}

__global__ void rope_k_kernel(const float* __restrict__ k,
                              const float* __restrict__ cosb,
                              const float* __restrict__ sinb) {
    int i = blockIdx.x * blockDim.x + threadIdx.x;
    const int total = BATCH * SEQ * HKV * (DH / 2);
    if (i >= total) return;
    int d    = i & 63;
    int rest = i >> 6;
    int h = rest % HKV;
    int s = (rest / HKV) % SEQ;
    int b = rest / (HKV * SEQ);

    size_t in_base = ((size_t)(b * SEQ + s) * HKV + h) * DH;
    float x0 = k[in_base + d];
    float x1 = k[in_base + d + 64];
    float c  = cosb[s * DH + d];
    float sn = sinb[s * DH + d];

    size_t out_base = ((size_t)(b * HKV + h) * SEQ + s) * DH;
    g_Kr[out_base + d]      = x0 * c - x1 * sn;
    g_Kr[out_base + d + 64] = x1 * c + x0 * sn;
}

__global__ void copy_v_kernel(const float* __restrict__ v) {
    int i = blockIdx.x * blockDim.x + threadIdx.x;        // index over float4s
    const int total = BATCH * SEQ * HKV * (DH / 4);
    if (i >= total) return;
    int d4   = i % (DH / 4);
    int rest = i / (DH / 4);
    int h = rest % HKV;
    int s = (rest / HKV) % SEQ;
    int b = rest / (HKV * SEQ);

    const float4 val = *(const float4*)(v + ((size_t)(b * SEQ + s) * HKV + h) * DH + 4 * d4);
    *(float4*)(g_Vr + ((size_t)(b * HKV + h) * SEQ + s) * DH + 4 * d4) = val;
}

// ---------------------------------------------------------------------------
// Flash attention: one CTA per (b, h, q-tile of 64 rows), 256 threads.
// Thread (ty=tid/16, tx=tid%16): 4x4 score microtile, 4x8 output microtile.
// Q,K tiles stored TRANSPOSED in smem ([kk][row]) so the score GEMM reads are
// broadcast (Q) / contiguous (K) -> conflict-free LDS.128.
// ---------------------------------------------------------------------------
__global__ __launch_bounds__(256, 1)
void flash_kernel(float* __restrict__ out, const float* __restrict__ scale_ptr) {
    extern __shared__ float smem[];
    float* Qt = smem;                           // [128][QT_STRIDE]
    float* Kt = Qt + DH * QT_STRIDE;            // [128][QT_STRIDE]
    float* Vs = Kt + DH * QT_STRIDE;            // [64][128]
    float* Ps = Vs + BK * DH;                   // [64][PS_STRIDE]

    const int tid = threadIdx.x;
    const int w   = tid >> 5;
    const int l   = tid & 31;
    const int tx  = tid & 15;
    const int ty  = tid >> 4;

    const int qb = blockIdx.x & (SEQ / BQ - 1);
    const int h  = (blockIdx.x >> 5) & (HQ - 1);
    const int b  = blockIdx.x >> 10;
    const int hk = h / GROUPS;

    const float scale = *scale_ptr;

    const float* Qg = g_Qr + ((size_t)(b * HQ + h) * SEQ + (size_t)qb * BQ) * DH;
    const float* Kg = g_Kr + (size_t)(b * HKV + hk) * SEQ * DH;
    const float* Vg = g_Vr + (size_t)(b * HKV + hk) * SEQ * DH;

    // ---- load Q tile transposed (coalesced gmem, <=2-way STS conflicts) ----
    {
        const int c     = 8 * w + (l >> 2);
        const int kbase = 4 * (l & 3);
        #pragma unroll
        for (int g = 0; g < 8; g++) {
            const int kk = 16 * g + kbase;
            float4 val = *(const float4*)(Qg + c * DH + kk);
            Qt[(kk + 0) * QT_STRIDE + c] = val.x;
            Qt[(kk + 1) * QT_STRIDE + c] = val.y;
            Qt[(kk + 2) * QT_STRIDE + c] = val.z;
            Qt[(kk + 3) * QT_STRIDE + c] = val.w;
        }
    }

    float o[4][8];
    #pragma unroll
    for (int i = 0; i < 4; i++)
        #pragma unroll
        for (int c = 0; c < 8; c++) o[i][c] = 0.0f;
    float mrow[4] = {-1e30f, -1e30f, -1e30f, -1e30f};
    float lrow[4] = {0.0f, 0.0f, 0.0f, 0.0f};

    const int ntiles = qb + 1;  // causal: only tiles with k <= q
    for (int kb = 0; kb < ntiles; kb++) {
        __syncthreads();  // prior-iter reads done; also covers Q-tile visibility

        // ---- load K tile transposed ----
        {
            const int c     = 8 * w + (l >> 2);
            const int kbase = 4 * (l & 3);
            #pragma unroll
            for (int g = 0; g < 8; g++) {
                const int kk = 16 * g + kbase;
                float4 val = *(const float4*)(Kg + ((size_t)kb * BK + c) * DH + kk);
                Kt[(kk + 0) * QT_STRIDE + c] = val.x;
                Kt[(kk + 1) * QT_STRIDE + c] = val.y;
                Kt[(kk + 2) * QT_STRIDE + c] = val.z;
                Kt[(kk + 3) * QT_STRIDE + c] = val.w;
            }
        }
        // ---- load V tile natural [s][d] ----
        {
            #pragma unroll
            for (int rr = 0; rr < 8; rr++) {
                const int row = 8 * w + rr;
                *(float4*)&Vs[row * DH + 4 * l] =
                    *(const float4*)(Vg + ((size_t)kb * BK + row) * DH + 4 * l);
            }
        }
        __syncthreads();

        // ---- scores: S = Q @ K^T (4x4 per thread) ----
        float s[4][4];
        #pragma unroll
        for (int i = 0; i < 4; i++)
            #pragma unroll
            for (int j = 0; j < 4; j++) s[i][j] = 0.0f;

        #pragma unroll 4
        for (int kk = 0; kk < DH; kk++) {
            const float4 qv = *(const float4*)&Qt[kk * QT_STRIDE + 4 * ty];
            const float4 kv = *(const float4*)&Kt[kk * QT_STRIDE + 4 * tx];
            s[0][0] += qv.x * kv.x; s[0][1] += qv.x * kv.y; s[0][2] += qv.x * kv.z; s[0][3] += qv.x * kv.w;
            s[1][0] += qv.y * kv.x; s[1][1] += qv.y * kv.y; s[1][2] += qv.y * kv.z; s[1][3] += qv.y * kv.w;
            s[2][0] += qv.z * kv.x; s[2][1] += qv.z * kv.y; s[2][2] += qv.z * kv.z; s[2][3] += qv.z * kv.w;
            s[3][0] += qv.w * kv.x; s[3][1] += qv.w * kv.y; s[3][2] += qv.w * kv.z; s[3][3] += qv.w * kv.w;
        }

        // ---- scale + causal mask (only the diagonal tile can mask) ----
        const bool diag = (kb == qb);
        #pragma unroll
        for (int i = 0; i < 4; i++) {
            const int qg = qb * BQ + 4 * ty + i;
            #pragma unroll
            for (int j = 0; j < 4; j++) {
                float sv = s[i][j] * scale;
                if (diag && (kb * BK + 4 * tx + j) > qg) sv = -1e30f;
                s[i][j] = sv;
            }
        }

        // ---- online softmax (row reduction across the 16 tx lanes) ----
        #pragma unroll
        for (int i = 0; i < 4; i++) {
            float rm = fmaxf(fmaxf(s[i][0], s[i][1]), fmaxf(s[i][2], s[i][3]));
            #pragma unroll
            for (int off = 8; off >= 1; off >>= 1)
                rm = fmaxf(rm, __shfl_xor_sync(0xffffffffu, rm, off, 16));
            const float mn = fmaxf(mrow[i], rm);
            const float alpha = __expf(mrow[i] - mn);
            mrow[i] = mn;
            float rs = 0.0f;
            #pragma unroll
            for (int j = 0; j < 4; j++) {
                const float p = __expf(s[i][j] - mn);
                s[i][j] = p;
                rs += p;
            }
            #pragma unroll
            for (int off = 8; off >= 1; off >>= 1)
                rs += __shfl_xor_sync(0xffffffffu, rs, off, 16);
            lrow[i] = lrow[i] * alpha + rs;
            #pragma unroll
            for (int c = 0; c < 8; c++) o[i][c] *= alpha;
            *(float4*)&Ps[(4 * ty + i) * PS_STRIDE + 4 * tx] =
                make_float4(s[i][0], s[i][1], s[i][2], s[i][3]);
        }
        __syncthreads();

        // ---- O += P @ V (4x8 per thread) ----
        #pragma unroll 2
        for (int kk0 = 0; kk0 < BK; kk0 += 4) {
            float pA[4][4];
            #pragma unroll
            for (int i = 0; i < 4; i++) {
                const float4 pv = *(const float4*)&Ps[(4 * ty + i) * PS_STRIDE + kk0];
                pA[i][0] = pv.x; pA[i][1] = pv.y; pA[i][2] = pv.z; pA[i][3] = pv.w;
            }
            #pragma unroll
            for (int jj = 0; jj < 4; jj++) {
                const int kk = kk0 + jj;
                const float4 v0 = *(const float4*)&Vs[kk * DH + 8 * tx];
                const float4 v1 = *(const float4*)&Vs[kk * DH + 8 * tx + 4];
                #pragma unroll
                for (int i = 0; i < 4; i++) {
                    const float p = pA[i][jj];
                    o[i][0] += p * v0.x; o[i][1] += p * v0.y;
                    o[i][2] += p * v0.z; o[i][3] += p * v0.w;
                    o[i][4] += p * v1.x; o[i][5] += p * v1.y;
                    o[i][6] += p * v1.z; o[i][7] += p * v1.w;
                }
            }
        }
    }

    // ---- epilogue: out[b, q, h, d] = o / l ----
    #pragma unroll
    for (int i = 0; i < 4; i++) {
        const float inv = 1.0f / lrow[i];
        const int q_glob = qb * BQ + 4 * ty + i;
        float* Og = out + ((size_t)(b * SEQ + q_glob) * HQ + h) * DH;
        *(float4*)(Og + 8 * tx) =
            make_float4(o[i][0] * inv, o[i][1] * inv, o[i][2] * inv, o[i][3] * inv);
        *(float4*)(Og + 8 * tx + 4) =
            make_float4(o[i][4] * inv, o[i][5] * inv, o[i][6] * inv, o[i][7] * inv);
    }
}

// ---------------------------------------------------------------------------
extern "C" void kernel_launch(void* const* d_in, const int* in_sizes, int n_in,
                              void* d_out, int out_size) {
    const float* q     = (const float*)d_in[0];
    const float* k     = (const float*)d_in[1];
    const float* v     = (const float*)d_in[2];
    const float* cosb  = (const float*)d_in[3];
    const float* sinb  = (const float*)d_in[4];
    // d_in[5] = attention_mask (exact causal; applied analytically in-kernel)
    const float* scale = (const float*)d_in[6];
    float* out = (float*)d_out;

    {
        const int total = BATCH * SEQ * HQ * (DH / 2);
        rope_q_kernel<<<(total + 255) / 256, 256>>>(q, cosb, sinb);
    }
    {
        const int total = BATCH * SEQ * HKV * (DH / 2);
        rope_k_kernel<<<(total + 255) / 256, 256>>>(k, cosb, sinb);
    }
    {
        const int total = BATCH * SEQ * HKV * (DH / 4);
        copy_v_kernel<<<(total + 255) / 256, 256>>>(v);
    }

    const int smem_bytes = (DH * QT_STRIDE * 2 + BK * DH + BQ * PS_STRIDE) * (int)sizeof(float);
    cudaFuncSetAttribute(flash_kernel, cudaFuncAttributeMaxDynamicSharedMemorySize, smem_bytes);
    flash_kernel<<<BATCH * HQ * (SEQ / BQ), 256, smem_bytes>>>(out, scale);
}

// round 2
// speedup vs baseline: 4.0630x; 4.0630x over previous
#include <cuda_runtime.h>
#include <math.h>
#include <stdint.h>

#define BATCH 2
#define SEQ   2048
#define HQ    32
#define HKV   8
#define DH    128

#define BQ 256
#define BK 64
#define QS_STRIDE 136
#define KS_STRIDE 136
#define VS_STRIDE 132

#define QS_FLOATS (BQ * QS_STRIDE)
#define KS_FLOATS (BK * KS_STRIDE)
#define VS_FLOATS (BK * VS_STRIDE)
#define SMEM_FLOATS (QS_FLOATS + KS_FLOATS + VS_FLOATS)

__device__ __forceinline__ float tf32r(float x) {
    uint32_t u;
    asm("cvt.rna.tf32.f32 %0, %1;" : "=r"(u) : "f"(x));
    return __uint_as_float(u);
}
__device__ __forceinline__ float ex2(float x) {
    float r;
    asm("ex2.approx.f32 %0, %1;" : "=f"(r) : "f"(x));
    return r;
}
// pair-permutation: within each 8-col group, put cols (c, c+4) adjacent
__device__ __forceinline__ int pcol(int k) {
    return (k & ~7) | ((k & 3) << 1) | ((k >> 2) & 1);
}
__device__ __forceinline__ void mma8(float c[4], float a0, float a1, float a2, float a3,
                                     float b0, float b1) {
    asm volatile(
        "mma.sync.aligned.m16n8k8.row.col.f32.tf32.tf32.f32 "
        "{%0,%1,%2,%3}, {%4,%5,%6,%7}, {%8,%9}, {%0,%1,%2,%3};"
        : "+f"(c[0]), "+f"(c[1]), "+f"(c[2]), "+f"(c[3])
        : "r"(__float_as_uint(a0)), "r"(__float_as_uint(a1)),
          "r"(__float_as_uint(a2)), "r"(__float_as_uint(a3)),
          "r"(__float_as_uint(b0)), "r"(__float_as_uint(b1)));
}

// ---------------------------------------------------------------------------
// One CTA = (b, h, 256 q-rows). 8 warps, each warp owns 32 rows (2 m16 tiles).
// Q (RoPE'd, scaled, tf32) stationary in smem. K/V tiles streamed per 64-col
// k-tile with RoPE fused into the fill. P stays in registers (shfl permute).
// ---------------------------------------------------------------------------
__global__ __launch_bounds__(256, 1)
void flash_tf32_kernel(const float* __restrict__ q, const float* __restrict__ k,
                       const float* __restrict__ v, const float* __restrict__ cosb,
                       const float* __restrict__ sinb,
                       const float* __restrict__ scale_ptr,
                       float* __restrict__ out) {
    extern __shared__ float sm[];
    float* Qs = sm;
    float* Ks = sm + QS_FLOATS;
    float* Vs = Ks + KS_FLOATS;

    const int tid  = threadIdx.x;
    const int w    = tid >> 5;
    const int lane = tid & 31;
    const int g    = lane >> 2;   // groupID (row within m8)
    const int tig  = lane & 3;    // thread in group (k/col lane)

    const int qb = 7 - blockIdx.x;        // heavy q-tiles first
    const int h  = blockIdx.y;
    const int b  = blockIdx.z;
    const int hk = h >> 2;                 // GROUPS = 4

    const float scale2 = (*scale_ptr) * 1.4426950408889634f;  // log2(e) folded in

    // ---- Q fill: RoPE + scale + tf32-round + pair-permuted store ----
    #pragma unroll 1
    for (int it = 0; it < 16; it++) {
        int idx = it * 256 + tid;
        int r   = idx >> 4;
        int c4  = (idx & 15) << 2;            // [0,64)
        int qrow = qb * BQ + r;
        const float* qp = q + ((size_t)(b * SEQ + qrow) * HQ + h) * DH;
        float4 x0 = *(const float4*)(qp + c4);
        float4 x1 = *(const float4*)(qp + c4 + 64);
        float4 cs = *(const float4*)(cosb + (size_t)qrow * DH + c4);
        float4 sn = *(const float4*)(sinb + (size_t)qrow * DH + c4);
        float* Qrow = Qs + r * QS_STRIDE;
        Qrow[pcol(c4 + 0)]      = tf32r((x0.x * cs.x - x1.x * sn.x) * scale2);
        Qrow[pcol(c4 + 1)]      = tf32r((x0.y * cs.y - x1.y * sn.y) * scale2);
        Qrow[pcol(c4 + 2)]      = tf32r((x0.z * cs.z - x1.z * sn.z) * scale2);
        Qrow[pcol(c4 + 3)]      = tf32r((x0.w * cs.w - x1.w * sn.w) * scale2);
        Qrow[pcol(c4 + 64 + 0)] = tf32r((x1.x * cs.x + x0.x * sn.x) * scale2);
        Qrow[pcol(c4 + 64 + 1)] = tf32r((x1.y * cs.y + x0.y * sn.y) * scale2);
        Qrow[pcol(c4 + 64 + 2)] = tf32r((x1.z * cs.z + x0.z * sn.z) * scale2);
        Qrow[pcol(c4 + 64 + 3)] = tf32r((x1.w * cs.w + x0.w * sn.w) * scale2);
    }

    float O[2][16][4];
    #pragma unroll
    for (int mi = 0; mi < 2; mi++)
        #pragma unroll
        for (int dj = 0; dj < 16; dj++)
            #pragma unroll
            for (int c = 0; c < 4; c++) O[mi][dj][c] = 0.0f;
    float mrow[2][2] = {{-1e30f, -1e30f}, {-1e30f, -1e30f}};
    float lrow[2][2] = {{0.0f, 0.0f}, {0.0f, 0.0f}};

    const int rb = 32 * w;
    const int nkt = 4 * qb + 4;

    for (int kb = 0; kb < nkt; kb++) {
        __syncthreads();   // prior-iter smem reads done (also orders Q fill on kb==0)

        // ---- K fill: RoPE + tf32 + pair-permuted ----
        #pragma unroll 1
        for (int it = 0; it < 4; it++) {
            int idx = it * 256 + tid;
            int r   = idx >> 4;
            int c4  = (idx & 15) << 2;
            int srow = kb * BK + r;
            const float* kp = k + ((size_t)(b * SEQ + srow) * HKV + hk) * DH;
            float4 x0 = *(const float4*)(kp + c4);
            float4 x1 = *(const float4*)(kp + c4 + 64);
            float4 cs = *(const float4*)(cosb + (size_t)srow * DH + c4);
            float4 sn = *(const float4*)(sinb + (size_t)srow * DH + c4);
            float* Krow = Ks + r * KS_STRIDE;
            Krow[pcol(c4 + 0)]      = tf32r(x0.x * cs.x - x1.x * sn.x);
            Krow[pcol(c4 + 1)]      = tf32r(x0.y * cs.y - x1.y * sn.y);
            Krow[pcol(c4 + 2)]      = tf32r(x0.z * cs.z - x1.z * sn.z);
            Krow[pcol(c4 + 3)]      = tf32r(x0.w * cs.w - x1.w * sn.w);
            Krow[pcol(c4 + 64 + 0)] = tf32r(x1.x * cs.x + x0.x * sn.x);
            Krow[pcol(c4 + 64 + 1)] = tf32r(x1.y * cs.y + x0.y * sn.y);
            Krow[pcol(c4 + 64 + 2)] = tf32r(x1.z * cs.z + x0.z * sn.z);
            Krow[pcol(c4 + 64 + 3)] = tf32r(x1.w * cs.w + x0.w * sn.w);
        }
        // ---- V fill: tf32 + d-permuted (d -> (d%8)*16 + d/8) ----
        #pragma unroll 1
        for (int it = 0; it < 8; it++) {
            int idx = it * 256 + tid;
            int r   = idx >> 5;
            int c4  = (idx & 31) << 2;
            const float* vp = v + ((size_t)(b * SEQ + kb * BK + r) * HKV + hk) * DH;
            float4 val = *(const float4*)(vp + c4);
            float* Vrow = Vs + r * VS_STRIDE;
            int hi = c4 >> 3;
            int lo = c4 & 7;
            Vrow[(lo + 0) * 16 + hi] = tf32r(val.x);
            Vrow[(lo + 1) * 16 + hi] = tf32r(val.y);
            Vrow[(lo + 2) * 16 + hi] = tf32r(val.z);
            Vrow[(lo + 3) * 16 + hi] = tf32r(val.w);
        }
        __syncthreads();

        const bool skip = (kb * BK > qb * BQ + rb + 31);  // tile fully above causal diag
        if (skip) continue;   // sync at loop top is still hit by all warps next iter

        // ---- scores: S[2 mtiles][8 ntiles] = Q @ K^T ----
        float S[2][8][4];
        #pragma unroll
        for (int mi = 0; mi < 2; mi++)
            #pragma unroll
            for (int j = 0; j < 8; j++)
                #pragma unroll
                for (int c = 0; c < 4; c++) S[mi][j][c] = 0.0f;

        #pragma unroll
        for (int s = 0; s < 16; s++) {
            float2 a0[2], a1[2];
            #pragma unroll
            for (int mi = 0; mi < 2; mi++) {
                a0[mi] = *(const float2*)&Qs[(rb + 16 * mi + g) * QS_STRIDE + 8 * s + 2 * tig];
                a1[mi] = *(const float2*)&Qs[(rb + 16 * mi + g + 8) * QS_STRIDE + 8 * s + 2 * tig];
            }
            #pragma unroll
            for (int j = 0; j < 8; j++) {
                float2 bb = *(const float2*)&Ks[(8 * j + g) * KS_STRIDE + 8 * s + 2 * tig];
                mma8(S[0][j], a0[0].x, a1[0].x, a0[0].y, a1[0].y, bb.x, bb.y);
                mma8(S[1][j], a0[1].x, a1[1].x, a0[1].y, a1[1].y, bb.x, bb.y);
            }
        }

        // ---- causal mask (only the last 4 tiles can touch the diagonal) ----
        if (kb >= 4 * qb) {
            #pragma unroll
            for (int mi = 0; mi < 2; mi++)
                #pragma unroll
                for (int j = 0; j < 8; j++)
                    #pragma unroll
                    for (int c = 0; c < 4; c++) {
                        int row = qb * BQ + rb + 16 * mi + g + ((c >> 1) ? 8 : 0);
                        int col = kb * BK + 8 * j + 2 * tig + (c & 1);
                        if (col > row) S[mi][j][c] = -3.0e38f;
                    }
        }

        // ---- online softmax (fragment-level; 4-lane groups own a full row) ----
        #pragma unroll
        for (int mi = 0; mi < 2; mi++)
            #pragma unroll
            for (int rr = 0; rr < 2; rr++) {
                float rm = -3.0e38f;
                #pragma unroll
                for (int j = 0; j < 8; j++)
                    rm = fmaxf(rm, fmaxf(S[mi][j][2 * rr], S[mi][j][2 * rr + 1]));
                rm = fmaxf(rm, __shfl_xor_sync(0xffffffffu, rm, 1));
                rm = fmaxf(rm, __shfl_xor_sync(0xffffffffu, rm, 2));
                float mo = mrow[mi][rr];
                float mn = fmaxf(mo, rm);
                float alpha = ex2(mo - mn);
                mrow[mi][rr] = mn;
                float ss = 0.0f;
                #pragma unroll
                for (int j = 0; j < 8; j++) {
                    float p0 = ex2(S[mi][j][2 * rr] - mn);
                    float p1 = ex2(S[mi][j][2 * rr + 1] - mn);
                    S[mi][j][2 * rr] = p0;
                    S[mi][j][2 * rr + 1] = p1;
                    ss += p0 + p1;
                }
                ss += __shfl_xor_sync(0xffffffffu, ss, 1);
                ss += __shfl_xor_sync(0xffffffffu, ss, 2);
                lrow[mi][rr] = lrow[mi][rr] * alpha + ss;
                #pragma unroll
                for (int dj = 0; dj < 16; dj++) {
                    O[mi][dj][2 * rr]     *= alpha;
                    O[mi][dj][2 * rr + 1] *= alpha;
                }
            }

        // ---- O += P @ V (P stays in regs; acc->A-frag via shfl permute) ----
        #pragma unroll
        for (int s = 0; s < 8; s++) {
            float A[2][4];
            #pragma unroll
            for (int mi = 0; mi < 2; mi++) {
                float c0 = tf32r(S[mi][s][0]);
                float c1 = tf32r(S[mi][s][1]);
                float c2 = tf32r(S[mi][s][2]);
                float c3 = tf32r(S[mi][s][3]);
                int base = lane & ~3;
                int s1 = base | (tig >> 1);
                int s2 = base | ((tig >> 1) + 2);
                float p00 = __shfl_sync(0xffffffffu, c0, s1);
                float p01 = __shfl_sync(0xffffffffu, c1, s1);
                float p10 = __shfl_sync(0xffffffffu, c2, s1);
                float p11 = __shfl_sync(0xffffffffu, c3, s1);
                float q00 = __shfl_sync(0xffffffffu, c0, s2);
                float q01 = __shfl_sync(0xffffffffu, c1, s2);
                float q10 = __shfl_sync(0xffffffffu, c2, s2);
                float q11 = __shfl_sync(0xffffffffu, c3, s2);
                bool odd = (tig & 1);
                A[mi][0] = odd ? p01 : p00;   // row g,   col tig
                A[mi][1] = odd ? p11 : p10;   // row g+8, col tig
                A[mi][2] = odd ? q01 : q00;   // row g,   col tig+4
                A[mi][3] = odd ? q11 : q10;   // row g+8, col tig+4
            }
            const float* Vr0 = Vs + (8 * s + tig) * VS_STRIDE + g * 16;
            const float* Vr1 = Vs + (8 * s + tig + 4) * VS_STRIDE + g * 16;
            #pragma unroll
            for (int dq = 0; dq < 4; dq++) {
                float4 b0v = *(const float4*)(Vr0 + 4 * dq);
                float4 b1v = *(const float4*)(Vr1 + 4 * dq);
                mma8(O[0][4 * dq + 0], A[0][0], A[0][1], A[0][2], A[0][3], b0v.x, b1v.x);
                mma8(O[1][4 * dq + 0], A[1][0], A[1][1], A[1][2], A[1][3], b0v.x, b1v.x);
                mma8(O[0][4 * dq + 1], A[0][0], A[0][1], A[0][2], A[0][3], b0v.y, b1v.y);
                mma8(O[1][4 * dq + 1], A[1][0], A[1][1], A[1][2], A[1][3], b0v.y, b1v.y);
                mma8(O[0][4 * dq + 2], A[0][0], A[0][1], A[0][2], A[0][3], b0v.z, b1v.z);
                mma8(O[1][4 * dq + 2], A[1][0], A[1][1], A[1][2], A[1][3], b0v.z, b1v.z);
                mma8(O[0][4 * dq + 3], A[0][0], A[0][1], A[0][2], A[0][3], b0v.w, b1v.w);
                mma8(O[1][4 * dq + 3], A[1][0], A[1][1], A[1][2], A[1][3], b0v.w, b1v.w);
            }
        }
    }

    // ---- epilogue: out[b, q, h, d] = O / l ----
    #pragma unroll
    for (int mi = 0; mi < 2; mi++)
        #pragma unroll
        for (int rr = 0; rr < 2; rr++) {
            float inv = 1.0f / lrow[mi][rr];
            int qrow = qb * BQ + rb + 16 * mi + g + 8 * rr;
            float* op = out + ((size_t)(b * SEQ + qrow) * HQ + h) * DH + 2 * tig;
            #pragma unroll
            for (int dj = 0; dj < 16; dj++) {
                float2 val = make_float2(O[mi][dj][2 * rr] * inv, O[mi][dj][2 * rr + 1] * inv);
                *(float2*)(op + 8 * dj) = val;
            }
        }
}

// ---------------------------------------------------------------------------
extern "C" void kernel_launch(void* const* d_in, const int* in_sizes, int n_in,
                              void* d_out, int out_size) {
    const float* q     = (const float*)d_in[0];
    const float* k     = (const float*)d_in[1];
    const float* v     = (const float*)d_in[2];
    const float* cosb  = (const float*)d_in[3];
    const float* sinb  = (const float*)d_in[4];
    // d_in[5] = attention_mask (exact causal; applied analytically in-kernel)
    const float* scale = (const float*)d_in[6];
    float* out = (float*)d_out;

    const int smem_bytes = SMEM_FLOATS * (int)sizeof(float);
    cudaFuncSetAttribute(flash_tf32_kernel,
                         cudaFuncAttributeMaxDynamicSharedMemorySize, smem_bytes);
    dim3 grid(SEQ / BQ, HQ, BATCH);
    flash_tf32_kernel<<<grid, 256, smem_bytes>>>(q, k, v, cosb, sinb, scale, out);
}

// round 3
// speedup vs baseline: 5.2673x; 1.2964x over previous
#include <cuda_runtime.h>
#include <math.h>
#include <stdint.h>

#define BATCH 2
#define SEQ   2048
#define HQ    32
#define HKV   8
#define DH    128

#define BQ 256
#define BK 64
#define NTHREADS 512
#define QS_STRIDE 136
#define KS_STRIDE 136
#define VS_STRIDE 132

#define QS_FLOATS (BQ * QS_STRIDE)
#define KS_FLOATS (BK * KS_STRIDE)
#define VS_FLOATS (BK * VS_STRIDE)
#define SMEM_FLOATS (QS_FLOATS + KS_FLOATS + VS_FLOATS)

__device__ __forceinline__ float tf32r(float x) {
    uint32_t u;
    asm("cvt.rna.tf32.f32 %0, %1;" : "=r"(u) : "f"(x));
    return __uint_as_float(u);
}
__device__ __forceinline__ float ex2(float x) {
    float r;
    asm("ex2.approx.f32 %0, %1;" : "=f"(r) : "f"(x));
    return r;
}
// pair-permutation: within each 8-col group, put cols (c, c+4) adjacent
__device__ __forceinline__ int pcol(int k) {
    return (k & ~7) | ((k & 3) << 1) | ((k >> 2) & 1);
}
__device__ __forceinline__ void mma8(float c[4], float a0, float a1, float a2, float a3,
                                     float b0, float b1) {
    asm volatile(
        "mma.sync.aligned.m16n8k8.row.col.f32.tf32.tf32.f32 "
        "{%0,%1,%2,%3}, {%4,%5,%6,%7}, {%8,%9}, {%0,%1,%2,%3};"
        : "+f"(c[0]), "+f"(c[1]), "+f"(c[2]), "+f"(c[3])
        : "r"(__float_as_uint(a0)), "r"(__float_as_uint(a1)),
          "r"(__float_as_uint(a2)), "r"(__float_as_uint(a3)),
          "r"(__float_as_uint(b0)), "r"(__float_as_uint(b1)));
}

// ---------------------------------------------------------------------------
// One CTA = (b, h, 256 q-rows). 16 warps, each warp owns ONE m16 tile
// (16 q-rows). Q (RoPE'd, scaled, tf32) stationary in smem; K/V streamed
// per 64-col k-tile with RoPE fused into the fill. P stays in registers.
// 512 threads -> 128 regs/thread budget; per-thread state ~120 regs.
// ---------------------------------------------------------------------------
__global__ __launch_bounds__(NTHREADS, 1)
void flash_tf32_kernel(const float* __restrict__ q, const float* __restrict__ k,
                       const float* __restrict__ v, const float* __restrict__ cosb,
                       const float* __restrict__ sinb,
                       const float* __restrict__ scale_ptr,
                       float* __restrict__ out) {
    extern __shared__ float sm[];
    float* Qs = sm;
    float* Ks = sm + QS_FLOATS;
    float* Vs = Ks + KS_FLOATS;

    const int tid  = threadIdx.x;
    const int w    = tid >> 5;
    const int lane = tid & 31;
    const int g    = lane >> 2;   // groupID (row within m8)
    const int tig  = lane & 3;    // thread in group

    const int qb = 7 - blockIdx.x;        // heavy q-tiles first
    const int h  = blockIdx.y;
    const int b  = blockIdx.z;
    const int hk = h >> 2;                 // GROUPS = 4

    const float scale2 = (*scale_ptr) * 1.4426950408889634f;  // fold log2(e)

    // ---- Q fill: RoPE + scale + tf32-round + pair-permuted store ----
    #pragma unroll 1
    for (int it = 0; it < 8; it++) {
        int idx = it * NTHREADS + tid;
        int r   = idx >> 4;
        int c4  = (idx & 15) << 2;            // [0,64)
        int qrow = qb * BQ + r;
        const float* qp = q + ((size_t)(b * SEQ + qrow) * HQ + h) * DH;
        float4 x0 = *(const float4*)(qp + c4);
        float4 x1 = *(const float4*)(qp + c4 + 64);
        float4 cs = *(const float4*)(cosb + (size_t)qrow * DH + c4);
        float4 sn = *(const float4*)(sinb + (size_t)qrow * DH + c4);
        float* Qrow = Qs + r * QS_STRIDE;
        Qrow[pcol(c4 + 0)]      = tf32r((x0.x * cs.x - x1.x * sn.x) * scale2);
        Qrow[pcol(c4 + 1)]      = tf32r((x0.y * cs.y - x1.y * sn.y) * scale2);
        Qrow[pcol(c4 + 2)]      = tf32r((x0.z * cs.z - x1.z * sn.z) * scale2);
        Qrow[pcol(c4 + 3)]      = tf32r((x0.w * cs.w - x1.w * sn.w) * scale2);
        Qrow[pcol(c4 + 64 + 0)] = tf32r((x1.x * cs.x + x0.x * sn.x) * scale2);
        Qrow[pcol(c4 + 64 + 1)] = tf32r((x1.y * cs.y + x0.y * sn.y) * scale2);
        Qrow[pcol(c4 + 64 + 2)] = tf32r((x1.z * cs.z + x0.z * sn.z) * scale2);
        Qrow[pcol(c4 + 64 + 3)] = tf32r((x1.w * cs.w + x0.w * sn.w) * scale2);
    }

    float O[16][4];
    #pragma unroll
    for (int dj = 0; dj < 16; dj++)
        #pragma unroll
        for (int c = 0; c < 4; c++) O[dj][c] = 0.0f;
    float mrow[2] = {-1e30f, -1e30f};
    float lrow[2] = {0.0f, 0.0f};

    const int rb = 16 * w;
    const int nkt = 4 * qb + 4;

    for (int kb = 0; kb < nkt; kb++) {
        __syncthreads();   // prior-iter smem reads done (also orders Q fill)

        // ---- K fill: RoPE + tf32 + pair-permuted ----
        #pragma unroll 1
        for (int it = 0; it < 2; it++) {
            int idx = it * NTHREADS + tid;
            int r   = idx >> 4;
            int c4  = (idx & 15) << 2;
            int srow = kb * BK + r;
            const float* kp = k + ((size_t)(b * SEQ + srow) * HKV + hk) * DH;
            float4 x0 = *(const float4*)(kp + c4);
            float4 x1 = *(const float4*)(kp + c4 + 64);
            float4 cs = *(const float4*)(cosb + (size_t)srow * DH + c4);
            float4 sn = *(const float4*)(sinb + (size_t)srow * DH + c4);
            float* Krow = Ks + r * KS_STRIDE;
            Krow[pcol(c4 + 0)]      = tf32r(x0.x * cs.x - x1.x * sn.x);
            Krow[pcol(c4 + 1)]      = tf32r(x0.y * cs.y - x1.y * sn.y);
            Krow[pcol(c4 + 2)]      = tf32r(x0.z * cs.z - x1.z * sn.z);
            Krow[pcol(c4 + 3)]      = tf32r(x0.w * cs.w - x1.w * sn.w);
            Krow[pcol(c4 + 64 + 0)] = tf32r(x1.x * cs.x + x0.x * sn.x);
            Krow[pcol(c4 + 64 + 1)] = tf32r(x1.y * cs.y + x0.y * sn.y);
            Krow[pcol(c4 + 64 + 2)] = tf32r(x1.z * cs.z + x0.z * sn.z);
            Krow[pcol(c4 + 64 + 3)] = tf32r(x1.w * cs.w + x0.w * sn.w);
        }
        // ---- V fill: tf32 + d-permuted (d -> (d%8)*16 + d/8) ----
        #pragma unroll 1
        for (int it = 0; it < 4; it++) {
            int idx = it * NTHREADS + tid;
            int r   = idx >> 5;
            int c4  = (idx & 31) << 2;
            const float* vp = v + ((size_t)(b * SEQ + kb * BK + r) * HKV + hk) * DH;
            float4 val = *(const float4*)(vp + c4);
            float* Vrow = Vs + r * VS_STRIDE;
            int hi = c4 >> 3;
            int lo = c4 & 7;
            Vrow[(lo + 0) * 16 + hi] = tf32r(val.x);
            Vrow[(lo + 1) * 16 + hi] = tf32r(val.y);
            Vrow[(lo + 2) * 16 + hi] = tf32r(val.z);
            Vrow[(lo + 3) * 16 + hi] = tf32r(val.w);
        }
        __syncthreads();

        const bool skip = (kb * BK > qb * BQ + rb + 15);  // tile above causal diag
        if (skip) continue;   // loop-top sync still reached by all warps

        // ---- scores: S[8 ntiles] = Q @ K^T ----
        float S[8][4];
        #pragma unroll
        for (int j = 0; j < 8; j++)
            #pragma unroll
            for (int c = 0; c < 4; c++) S[j][c] = 0.0f;

        #pragma unroll
        for (int s = 0; s < 16; s++) {
            float2 a0 = *(const float2*)&Qs[(rb + g) * QS_STRIDE + 8 * s + 2 * tig];
            float2 a1 = *(const float2*)&Qs[(rb + g + 8) * QS_STRIDE + 8 * s + 2 * tig];
            #pragma unroll
            for (int j = 0; j < 8; j++) {
                float2 bb = *(const float2*)&Ks[(8 * j + g) * KS_STRIDE + 8 * s + 2 * tig];
                mma8(S[j], a0.x, a1.x, a0.y, a1.y, bb.x, bb.y);
            }
        }

        // ---- causal mask (only the last 4 tiles can touch the diagonal) ----
        if (kb >= 4 * qb) {
            #pragma unroll
            for (int j = 0; j < 8; j++)
                #pragma unroll
                for (int c = 0; c < 4; c++) {
                    int row = qb * BQ + rb + g + ((c >> 1) ? 8 : 0);
                    int col = kb * BK + 8 * j + 2 * tig + (c & 1);
                    if (col > row) S[j][c] = -3.0e38f;
                }
        }

        // ---- online softmax (4-lane groups own a full row) ----
        #pragma unroll
        for (int rr = 0; rr < 2; rr++) {
            float rm = -3.0e38f;
            #pragma unroll
            for (int j = 0; j < 8; j++)
                rm = fmaxf(rm, fmaxf(S[j][2 * rr], S[j][2 * rr + 1]));
            rm = fmaxf(rm, __shfl_xor_sync(0xffffffffu, rm, 1));
            rm = fmaxf(rm, __shfl_xor_sync(0xffffffffu, rm, 2));
            float mo = mrow[rr];
            float mn = fmaxf(mo, rm);
            float alpha = ex2(mo - mn);
            mrow[rr] = mn;
            float ss = 0.0f;
            #pragma unroll
            for (int j = 0; j < 8; j++) {
                float p0 = ex2(S[j][2 * rr] - mn);
                float p1 = ex2(S[j][2 * rr + 1] - mn);
                S[j][2 * rr] = p0;
                S[j][2 * rr + 1] = p1;
                ss += p0 + p1;
            }
            ss += __shfl_xor_sync(0xffffffffu, ss, 1);
            ss += __shfl_xor_sync(0xffffffffu, ss, 2);
            lrow[rr] = lrow[rr] * alpha + ss;
            #pragma unroll
            for (int dj = 0; dj < 16; dj++) {
                O[dj][2 * rr]     *= alpha;
                O[dj][2 * rr + 1] *= alpha;
            }
        }

        // ---- O += P @ V (P in regs; acc->A-frag via shfl permute) ----
        #pragma unroll
        for (int s = 0; s < 8; s++) {
            float c0 = tf32r(S[s][0]);
            float c1 = tf32r(S[s][1]);
            float c2 = tf32r(S[s][2]);
            float c3 = tf32r(S[s][3]);
            int base = lane & ~3;
            int s1 = base | (tig >> 1);
            int s2 = base | ((tig >> 1) + 2);
            float p00 = __shfl_sync(0xffffffffu, c0, s1);
            float p01 = __shfl_sync(0xffffffffu, c1, s1);
            float p10 = __shfl_sync(0xffffffffu, c2, s1);
            float p11 = __shfl_sync(0xffffffffu, c3, s1);
            float q00 = __shfl_sync(0xffffffffu, c0, s2);
            float q01 = __shfl_sync(0xffffffffu, c1, s2);
            float q10 = __shfl_sync(0xffffffffu, c2, s2);
            float q11 = __shfl_sync(0xffffffffu, c3, s2);
            bool odd = (tig & 1);
            float A0 = odd ? p01 : p00;   // row g,   col tig
            float A1 = odd ? p11 : p10;   // row g+8, col tig
            float A2 = odd ? q01 : q00;   // row g,   col tig+4
            float A3 = odd ? q11 : q10;   // row g+8, col tig+4

            const float* Vr0 = Vs + (8 * s + tig) * VS_STRIDE + g * 16;
            const float* Vr1 = Vs + (8 * s + tig + 4) * VS_STRIDE + g * 16;
            #pragma unroll
            for (int dq = 0; dq < 4; dq++) {
                float4 b0v = *(const float4*)(Vr0 + 4 * dq);
                float4 b1v = *(const float4*)(Vr1 + 4 * dq);
                mma8(O[4 * dq + 0], A0, A1, A2, A3, b0v.x, b1v.x);
                mma8(O[4 * dq + 1], A0, A1, A2, A3, b0v.y, b1v.y);
                mma8(O[4 * dq + 2], A0, A1, A2, A3, b0v.z, b1v.z);
                mma8(O[4 * dq + 3], A0, A1, A2, A3, b0v.w, b1v.w);
            }
        }
    }

    // ---- epilogue: out[b, q, h, d] = O / l ----
    #pragma unroll
    for (int rr = 0; rr < 2; rr++) {
        float inv = 1.0f / lrow[rr];
        int qrow = qb * BQ + rb + g + 8 * rr;
        float* op = out + ((size_t)(b * SEQ + qrow) * HQ + h) * DH + 2 * tig;
        #pragma unroll
        for (int dj = 0; dj < 16; dj++) {
            float2 val = make_float2(O[dj][2 * rr] * inv, O[dj][2 * rr + 1] * inv);
            *(float2*)(op + 8 * dj) = val;
        }
    }
}

// ---------------------------------------------------------------------------
extern "C" void kernel_launch(void* const* d_in, const int* in_sizes, int n_in,
                              void* d_out, int out_size) {
    const float* q     = (const float*)d_in[0];
    const float* k     = (const float*)d_in[1];
    const float* v     = (const float*)d_in[2];
    const float* cosb  = (const float*)d_in[3];
    const float* sinb  = (const float*)d_in[4];
    // d_in[5] = attention_mask (exact causal; applied analytically in-kernel)
    const float* scale = (const float*)d_in[6];
    float* out = (float*)d_out;

    const int smem_bytes = SMEM_FLOATS * (int)sizeof(float);
    cudaFuncSetAttribute(flash_tf32_kernel,
                         cudaFuncAttributeMaxDynamicSharedMemorySize, smem_bytes);
    dim3 grid(SEQ / BQ, HQ, BATCH);
    flash_tf32_kernel<<<grid, NTHREADS, smem_bytes>>>(q, k, v, cosb, sinb, scale, out);
}